// round 13
// baseline (speedup 1.0000x reference)
#include <cuda_runtime.h>
#include <cstdint>

typedef unsigned long long ull;

// ---- packed f32x2 helpers (sm_103a) ----
__device__ __forceinline__ ull ffma2(ull a, ull b, ull c) {
    ull d;
    asm("fma.rn.f32x2 %0, %1, %2, %3;" : "=l"(d) : "l"(a), "l"(b), "l"(c));
    return d;
}
__device__ __forceinline__ ull fmul2(ull a, ull b) {
    ull d;
    asm("mul.rn.f32x2 %0, %1, %2;" : "=l"(d) : "l"(a), "l"(b));
    return d;
}
__device__ __forceinline__ ull fadd2(ull a, ull b) {
    ull d;
    asm("add.rn.f32x2 %0, %1, %2;" : "=l"(d) : "l"(a), "l"(b));
    return d;
}
__device__ __forceinline__ ull pack2(float lo, float hi) {
    ull d;
    asm("mov.b64 %0, {%1, %2};" : "=l"(d) : "f"(lo), "f"(hi));
    return d;
}
__device__ __forceinline__ ull dup2(float v) { return pack2(v, v); }
__device__ __forceinline__ float2 unpack2(ull v) {
    float lo, hi;
    asm("mov.b64 {%0, %1}, %2;" : "=f"(lo), "=f"(hi) : "l"(v));
    return make_float2(lo, hi);
}
__device__ __forceinline__ ull shflx(ull v, int m) {
    return __shfl_xor_sync(0xffffffffu, v, m);
}

// ---- smem addr / mbarrier / bulk-async helpers ----
__device__ __forceinline__ uint32_t smem_u32(const void* p) {
    uint32_t a;
    asm("{ .reg .u64 t; cvta.to.shared.u64 t, %1; cvt.u32.u64 %0, t; }"
        : "=r"(a) : "l"(p));
    return a;
}
__device__ __forceinline__ void mbar_init(uint32_t a, uint32_t c) {
    asm volatile("mbarrier.init.shared.b64 [%0], %1;" :: "r"(a), "r"(c) : "memory");
}
__device__ __forceinline__ void mbar_expect_tx(uint32_t a, uint32_t bytes) {
    asm volatile("mbarrier.arrive.expect_tx.shared.b64 _, [%0], %1;"
                 :: "r"(a), "r"(bytes) : "memory");
}
__device__ __forceinline__ void mbar_arrive(uint32_t a) {
    asm volatile("mbarrier.arrive.release.cta.shared::cta.b64 _, [%0];"
                 :: "r"(a) : "memory");
}
__device__ __forceinline__ void mbar_wait_acq(uint32_t a, uint32_t parity) {
    asm volatile(
        "{\n\t.reg .pred P;\n\t"
        "W_%=:\n\t"
        "mbarrier.try_wait.parity.acquire.cta.shared::cta.b64 P, [%0], %1, 0x989680;\n\t"
        "@!P bra W_%=;\n\t}"
        :: "r"(a), "r"(parity) : "memory");
}
__device__ __forceinline__ void mbar_wait_rlx(uint32_t a, uint32_t parity) {
    asm volatile(
        "{\n\t.reg .pred P;\n\t"
        "W_%=:\n\t"
        "mbarrier.try_wait.parity.relaxed.cta.shared::cta.b64 P, [%0], %1, 0x989680;\n\t"
        "@!P bra W_%=;\n\t}"
        :: "r"(a), "r"(parity) : "memory");
}
__device__ __forceinline__ void bulk_g2s(uint32_t dst, const void* src,
                                         uint32_t bytes, uint32_t mbar) {
    asm volatile(
        "cp.async.bulk.shared::cta.global.mbarrier::complete_tx::bytes [%0], [%1], %2, [%3];"
        :: "r"(dst), "l"(src), "r"(bytes), "r"(mbar) : "memory");
}
__device__ __forceinline__ void fence_proxy_async_cta() {
    asm volatile("fence.proxy.async.shared::cta;" ::: "memory");
}

constexpr int D_DIM       = 1024;
constexpr int THREADS     = 256;
constexpr int NWARP       = 8;
constexpr int STAGE_ROWS  = 4;
constexpr int STAGE_BYTES = STAGE_ROWS * D_DIM * 4;     // 16 KB
constexpr int NSTAGE      = 2;
constexpr int BATCH       = 16;                         // rows per phase2/3 batch
constexpr int ROWS_PER_BLK = 64;
constexpr int NSTG_TOTAL  = ROWS_PER_BLK / STAGE_ROWS;  // 16
constexpr int NGRP        = 32;                         // 8-lane groups
constexpr int SLOTS       = BATCH * 3;                  // 48
constexpr int PSTRIDE     = SLOTS + 1;                  // 49

__global__ void __launch_bounds__(THREADS)
q6_kernel(const float* __restrict__ x,
          const float* __restrict__ W,
          const float* __restrict__ proto,
          const float* __restrict__ hs,
          float* __restrict__ out)
{
    __shared__ __align__(128) char sx[NSTAGE][STAGE_BYTES];  // 32 KB x ring
    __shared__ ull    part[NGRP * PSTRIDE];                  // 12.5 KB
    __shared__ ull    zz[SLOTS];
    __shared__ float  pn[8][6];
    __shared__ float  s3_sh;
    __shared__ __align__(8) ull mbar[2 * NSTAGE];  // full[0..1], empty[2..3]

    const int tid  = threadIdx.x;
    const int lane = tid & 31;
    const int warp = tid >> 5;
    const int col  = tid * 4;             // this thread owns columns [col, col+4)

    const uint32_t mb   = smem_u32(mbar);
    const uint32_t sxa  = smem_u32(&sx[0][0]);

    // ---- one-time init ----
    if (tid < 8) {
        float v[6]; float ss = 0.f;
        #pragma unroll
        for (int k = 0; k < 6; ++k) { v[k] = proto[tid * 6 + k]; ss += v[k] * v[k]; }
        float n = fmaxf(sqrtf(ss), 1e-12f);
        #pragma unroll
        for (int k = 0; k < 6; ++k) pn[tid][k] = v[k] / n;
    }
    if (tid == 8) s3_sh = 3.0f * hs[0];   // softmax(-hs*(6-6d)/2) == softmax(3*hs*d)
    if (tid == 0) {
        mbar_init(mb + 0,  1);    // full[0]: expect_tx arrival only
        mbar_init(mb + 8,  1);    // full[1]
        mbar_init(mb + 16, NWARP);  // empty[0]: one arrive per warp
        mbar_init(mb + 24, NWARP);  // empty[1]
    }

    // ---- W slice: 4 columns, packed (k0,k1),(k2,k3),(k4,k5) ----
    ull wp[4][3];
    {
        float4 w4[6];
        #pragma unroll
        for (int k = 0; k < 6; ++k)
            w4[k] = *reinterpret_cast<const float4*>(W + k * D_DIM + col);
        #pragma unroll
        for (int p = 0; p < 3; ++p) {
            wp[0][p] = pack2(w4[2*p].x, w4[2*p+1].x);
            wp[1][p] = pack2(w4[2*p].y, w4[2*p+1].y);
            wp[2][p] = pack2(w4[2*p].z, w4[2*p+1].z);
            wp[3][p] = pack2(w4[2*p].w, w4[2*p+1].w);
        }
    }

    __syncthreads();                 // mbarrier init visible CTA-wide
    const int    rowbase = blockIdx.x * ROWS_PER_BLK;
    const float* xg      = x + (size_t)rowbase * D_DIM;

    if (tid == 0) {
        fence_proxy_async_cta();     // order init vs async proxy
        // prologue: fill both stages
        mbar_expect_tx(mb + 0, STAGE_BYTES);
        bulk_g2s(sxa, xg, STAGE_BYTES, mb + 0);
        mbar_expect_tx(mb + 8, STAGE_BYTES);
        bulk_g2s(sxa + STAGE_BYTES, xg + STAGE_ROWS * D_DIM, STAGE_BYTES, mb + 8);
    }

    #pragma unroll 1
    for (int b = 0; b < ROWS_PER_BLK / BATCH; ++b) {
        #pragma unroll
        for (int st = 0; st < 4; ++st) {
            const int g = b * 4 + st;         // global stage id
            const int s = g & 1;

            mbar_wait_acq(mb + s * 8, (g >> 1) & 1);   // stage resident

            float4 xv[4];
            #pragma unroll
            for (int r = 0; r < 4; ++r)
                xv[r] = *reinterpret_cast<const float4*>(
                    &sx[s][r * (D_DIM * 4) + tid * 16]);

            __syncwarp();
            if (lane == 0) mbar_arrive(mb + 16 + s * 8);   // warp done with slot

            if (tid == 0) {                    // refill this slot 2 stages ahead
                const int gn = g + NSTAGE;
                if (gn < NSTG_TOTAL) {
                    mbar_wait_rlx(mb + 16 + s * 8, ((gn >> 1) - 1) & 1);
                    mbar_expect_tx(mb + s * 8, STAGE_BYTES);
                    bulk_g2s(sxa + s * STAGE_BYTES,
                             xg + (size_t)gn * STAGE_ROWS * D_DIM,
                             STAGE_BYTES, mb + s * 8);
                }
            }

            // ---- compute 4 rows: 12 FFMA2 + 3-round butterfly each ----
            #pragma unroll
            for (int r = 0; r < 4; ++r) {
                ull xx = dup2(xv[r].x);
                ull a0 = fmul2(xx, wp[0][0]);
                ull a1 = fmul2(xx, wp[0][1]);
                ull a2 = fmul2(xx, wp[0][2]);
                xx = dup2(xv[r].y);
                a0 = ffma2(xx, wp[1][0], a0);
                a1 = ffma2(xx, wp[1][1], a1);
                a2 = ffma2(xx, wp[1][2], a2);
                xx = dup2(xv[r].z);
                a0 = ffma2(xx, wp[2][0], a0);
                a1 = ffma2(xx, wp[2][1], a1);
                a2 = ffma2(xx, wp[2][2], a2);
                xx = dup2(xv[r].w);
                a0 = ffma2(xx, wp[3][0], a0);
                a1 = ffma2(xx, wp[3][1], a1);
                a2 = ffma2(xx, wp[3][2], a2);

                a0 = fadd2(a0, shflx(a0, 1));
                a1 = fadd2(a1, shflx(a1, 1));
                a2 = fadd2(a2, shflx(a2, 1));
                a0 = fadd2(a0, shflx(a0, 2));
                a1 = fadd2(a1, shflx(a1, 2));
                a2 = fadd2(a2, shflx(a2, 2));
                a0 = fadd2(a0, shflx(a0, 4));
                a1 = fadd2(a1, shflx(a1, 4));
                a2 = fadd2(a2, shflx(a2, 4));

                if ((lane & 7) == 0) {
                    const int grp = warp * 4 + (lane >> 3);     // 0..31
                    ull* dst = part + grp * PSTRIDE + (st * 4 + r) * 3;
                    dst[0] = a0; dst[1] = a1; dst[2] = a2;
                }
            }
        }

        __syncthreads();   // all partials of batch b visible

        // ---- phase 2: 48 threads sum 32 group partials per (row, pair) ----
        if (tid < SLOTS) {
            ull s0 = 0ull, s1 = 0ull, s2 = 0ull, s3v = 0ull;
            #pragma unroll
            for (int gi = 0; gi < NGRP; gi += 4) {
                s0  = fadd2(s0,  part[(gi + 0) * PSTRIDE + tid]);
                s1  = fadd2(s1,  part[(gi + 1) * PSTRIDE + tid]);
                s2  = fadd2(s2,  part[(gi + 2) * PSTRIDE + tid]);
                s3v = fadd2(s3v, part[(gi + 3) * PSTRIDE + tid]);
            }
            zz[tid] = fadd2(fadd2(s0, s1), fadd2(s2, s3v));
        }
        __syncthreads();   // zz visible; gates part reuse by next batch

        // ---- phase 3: one thread per row (TMA keeps streaming meanwhile) ----
        if (tid < BATCH) {
            float z[6];
            #pragma unroll
            for (int p = 0; p < 3; ++p) {
                float2 v = unpack2(zz[tid * 3 + p]);
                z[2*p] = v.x; z[2*p + 1] = v.y;
            }
            float ss = 0.f;
            #pragma unroll
            for (int k = 0; k < 6; ++k) { z[k] = tanhf(z[k]); ss += z[k] * z[k]; }
            const float sc = s3_sh / fmaxf(sqrtf(ss), 1e-6f);

            float e[8]; float sum = 0.f;
            #pragma unroll
            for (int p = 0; p < 8; ++p) {
                float d = 0.f;
                #pragma unroll
                for (int k = 0; k < 6; ++k) d += z[k] * pn[p][k];
                e[p] = __expf(sc * d);
                sum += e[p];
            }
            const float rs  = 1.0f / sum;
            const int   row = rowbase + b * BATCH + tid;
            float4* op = reinterpret_cast<float4*>(out + (size_t)row * 8);
            op[0] = make_float4(e[0]*rs, e[1]*rs, e[2]*rs, e[3]*rs);
            op[1] = make_float4(e[4]*rs, e[5]*rs, e[6]*rs, e[7]*rs);
        }
    }
}

extern "C" void kernel_launch(void* const* d_in, const int* in_sizes, int n_in,
                              void* d_out, int out_size) {
    const float* x     = (const float*)d_in[0];
    const float* W     = (const float*)d_in[1];
    const float* proto = (const float*)d_in[2];
    const float* hs    = (const float*)d_in[3];
    float* out = (float*)d_out;

    const int n_rows = in_sizes[0] / D_DIM;          // 32768
    const int grid   = n_rows / ROWS_PER_BLK;        // 512
    q6_kernel<<<grid, THREADS>>>(x, W, proto, hs, out);
}

// round 14
// speedup vs baseline: 1.5349x; 1.5349x over previous
#include <cuda_runtime.h>
#include <cstdint>

typedef unsigned long long ull;

// ---- packed f32x2 helpers (sm_103a) ----
__device__ __forceinline__ ull ffma2(ull a, ull b, ull c) {
    ull d;
    asm("fma.rn.f32x2 %0, %1, %2, %3;" : "=l"(d) : "l"(a), "l"(b), "l"(c));
    return d;
}
__device__ __forceinline__ ull fmul2(ull a, ull b) {
    ull d;
    asm("mul.rn.f32x2 %0, %1, %2;" : "=l"(d) : "l"(a), "l"(b));
    return d;
}
__device__ __forceinline__ ull fadd2(ull a, ull b) {
    ull d;
    asm("add.rn.f32x2 %0, %1, %2;" : "=l"(d) : "l"(a), "l"(b));
    return d;
}
__device__ __forceinline__ ull pack2(float lo, float hi) {
    ull d;
    asm("mov.b64 %0, {%1, %2};" : "=l"(d) : "f"(lo), "f"(hi));
    return d;
}
__device__ __forceinline__ ull dup2(float v) { return pack2(v, v); }
__device__ __forceinline__ float2 unpack2(ull v) {
    float lo, hi;
    asm("mov.b64 {%0, %1}, %2;" : "=f"(lo), "=f"(hi) : "l"(v));
    return make_float2(lo, hi);
}
__device__ __forceinline__ ull shflx(ull v, int m) {
    return __shfl_xor_sync(0xffffffffu, v, m);
}

constexpr int D_DIM        = 1024;
constexpr int THREADS      = 256;
constexpr int ROWS_PER_BLK = 32;       // one batch per CTA; grid 1024 → ~1% wave quantization
constexpr int NGRP         = 32;       // 8-lane groups over 256 threads
constexpr int SLOTS        = ROWS_PER_BLK * 3;   // 96 (row, f32x2-pair)
constexpr int PSTRIDE      = SLOTS + 1;          // 97, odd → conflict-free columns

__global__ void __launch_bounds__(THREADS)
q6_kernel(const float* __restrict__ x,
          const float* __restrict__ W,
          const float* __restrict__ proto,
          const float* __restrict__ hs,
          float* __restrict__ out)
{
    // partials: [g=0..31][row*3+pair]
    __shared__ ull   part[NGRP * PSTRIDE];       // 24.8 KB
    __shared__ ull   zz[SLOTS];
    __shared__ float pn[8][6];
    __shared__ float s3_sh;

    const int tid  = threadIdx.x;
    const int lane = tid & 31;
    const int warp = tid >> 5;
    const int col  = tid * 4;        // this thread owns columns [col, col+4)

    // ---- one-time init (visible after phase-1 barrier) ----
    if (tid < 8) {
        float v[6]; float ss = 0.f;
        #pragma unroll
        for (int k = 0; k < 6; ++k) { v[k] = proto[tid * 6 + k]; ss += v[k] * v[k]; }
        float n = fmaxf(sqrtf(ss), 1e-12f);
        #pragma unroll
        for (int k = 0; k < 6; ++k) pn[tid][k] = v[k] / n;
    }
    if (tid == 8) s3_sh = 3.0f * hs[0];   // softmax(-hs*(6-6d)/2) == softmax(3*hs*d)

    // ---- W slice for this thread's 4 columns (L2-hot), packed pairs ----
    ull wp[4][3];
    {
        float4 w4[6];
        #pragma unroll
        for (int k = 0; k < 6; ++k)
            w4[k] = __ldg(reinterpret_cast<const float4*>(W + k * D_DIM + col));
        #pragma unroll
        for (int p = 0; p < 3; ++p) {
            wp[0][p] = pack2(w4[2*p].x, w4[2*p+1].x);
            wp[1][p] = pack2(w4[2*p].y, w4[2*p+1].y);
            wp[2][p] = pack2(w4[2*p].z, w4[2*p+1].z);
            wp[3][p] = pack2(w4[2*p].w, w4[2*p+1].w);
        }
    }

    const int    r0 = blockIdx.x * ROWS_PER_BLK;
    const float* xp = x + (size_t)r0 * D_DIM + col;

    // ---------------- phase 1: 8 bursts of 4 rows (R1 duty cycle) ----------------
    #pragma unroll
    for (int r = 0; r < ROWS_PER_BLK; r += 4) {
        float4 xv[4];
        #pragma unroll
        for (int u = 0; u < 4; ++u)   // 4 streaming loads back-to-back -> MLP=4
            xv[u] = __ldcs(reinterpret_cast<const float4*>(xp + (size_t)(r + u) * D_DIM));
        #pragma unroll
        for (int u = 0; u < 4; ++u) {
            ull xx = dup2(xv[u].x);
            ull a0 = fmul2(xx, wp[0][0]);
            ull a1 = fmul2(xx, wp[0][1]);
            ull a2 = fmul2(xx, wp[0][2]);
            xx = dup2(xv[u].y);
            a0 = ffma2(xx, wp[1][0], a0);
            a1 = ffma2(xx, wp[1][1], a1);
            a2 = ffma2(xx, wp[1][2], a2);
            xx = dup2(xv[u].z);
            a0 = ffma2(xx, wp[2][0], a0);
            a1 = ffma2(xx, wp[2][1], a1);
            a2 = ffma2(xx, wp[2][2], a2);
            xx = dup2(xv[u].w);
            a0 = ffma2(xx, wp[3][0], a0);
            a1 = ffma2(xx, wp[3][1], a1);
            a2 = ffma2(xx, wp[3][2], a2);

            // 3-round butterfly: lane%8==0 holds 8-lane (32-column) group sum
            a0 = fadd2(a0, shflx(a0, 1));
            a1 = fadd2(a1, shflx(a1, 1));
            a2 = fadd2(a2, shflx(a2, 1));
            a0 = fadd2(a0, shflx(a0, 2));
            a1 = fadd2(a1, shflx(a1, 2));
            a2 = fadd2(a2, shflx(a2, 2));
            a0 = fadd2(a0, shflx(a0, 4));
            a1 = fadd2(a1, shflx(a1, 4));
            a2 = fadd2(a2, shflx(a2, 4));

            if ((lane & 7) == 0) {
                const int g = warp * 4 + (lane >> 3);   // 0..31
                ull* dst = part + g * PSTRIDE + (r + u) * 3;
                dst[0] = a0; dst[1] = a1; dst[2] = a2;
            }
        }
    }
    __syncthreads();

    // ---------------- phase 2: 96 threads sum 32 group partials per slot ------
    if (tid < SLOTS) {
        ull s0 = 0ull, s1 = 0ull, s2 = 0ull, s3v = 0ull;
        #pragma unroll
        for (int g = 0; g < NGRP; g += 4) {
            s0  = fadd2(s0,  part[(g + 0) * PSTRIDE + tid]);
            s1  = fadd2(s1,  part[(g + 1) * PSTRIDE + tid]);
            s2  = fadd2(s2,  part[(g + 2) * PSTRIDE + tid]);
            s3v = fadd2(s3v, part[(g + 3) * PSTRIDE + tid]);
        }
        zz[tid] = fadd2(fadd2(s0, s1), fadd2(s2, s3v));
    }
    __syncthreads();

    // ---------------- phase 3: epilogue, one thread per row --------------------
    // (tail overlaps other resident CTAs' streaming via the HW scheduler)
    if (tid < ROWS_PER_BLK) {
        float z[6];
        #pragma unroll
        for (int p = 0; p < 3; ++p) {
            float2 v = unpack2(zz[tid * 3 + p]);
            z[2*p] = v.x; z[2*p + 1] = v.y;
        }
        float ss = 0.f;
        #pragma unroll
        for (int k = 0; k < 6; ++k) { z[k] = tanhf(z[k]); ss += z[k] * z[k]; }
        const float sc = s3_sh / fmaxf(sqrtf(ss), 1e-6f);

        float e[8]; float sum = 0.f;
        #pragma unroll
        for (int p = 0; p < 8; ++p) {
            float d = 0.f;
            #pragma unroll
            for (int k = 0; k < 6; ++k) d += z[k] * pn[p][k];
            e[p] = __expf(sc * d);
            sum += e[p];
        }
        const float rs  = 1.0f / sum;
        const int   row = r0 + tid;
        float4* op = reinterpret_cast<float4*>(out + (size_t)row * 8);
        op[0] = make_float4(e[0]*rs, e[1]*rs, e[2]*rs, e[3]*rs);
        op[1] = make_float4(e[4]*rs, e[5]*rs, e[6]*rs, e[7]*rs);
    }
}

extern "C" void kernel_launch(void* const* d_in, const int* in_sizes, int n_in,
                              void* d_out, int out_size) {
    const float* x     = (const float*)d_in[0];
    const float* W     = (const float*)d_in[1];
    const float* proto = (const float*)d_in[2];
    const float* hs    = (const float*)d_in[3];
    float* out = (float*)d_out;

    const int n_rows = in_sizes[0] / D_DIM;          // 32768
    const int grid   = n_rows / ROWS_PER_BLK;        // 1024
    q6_kernel<<<grid, THREADS>>>(x, W, proto, hs, out);
}

// round 15
// speedup vs baseline: 1.8501x; 1.2054x over previous
#include <cuda_runtime.h>
#include <cstdint>

typedef unsigned long long ull;

// ---- packed f32x2 helpers (sm_103a) ----
__device__ __forceinline__ ull ffma2(ull a, ull b, ull c) {
    ull d;
    asm("fma.rn.f32x2 %0, %1, %2, %3;" : "=l"(d) : "l"(a), "l"(b), "l"(c));
    return d;
}
__device__ __forceinline__ ull fmul2(ull a, ull b) {
    ull d;
    asm("mul.rn.f32x2 %0, %1, %2;" : "=l"(d) : "l"(a), "l"(b));
    return d;
}
__device__ __forceinline__ ull fadd2(ull a, ull b) {
    ull d;
    asm("add.rn.f32x2 %0, %1, %2;" : "=l"(d) : "l"(a), "l"(b));
    return d;
}
__device__ __forceinline__ ull pack2(float lo, float hi) {
    ull d;
    asm("mov.b64 %0, {%1, %2};" : "=l"(d) : "f"(lo), "f"(hi));
    return d;
}
__device__ __forceinline__ ull dup2(float v) { return pack2(v, v); }
__device__ __forceinline__ float2 unpack2(ull v) {
    float lo, hi;
    asm("mov.b64 {%0, %1}, %2;" : "=f"(lo), "=f"(hi) : "l"(v));
    return make_float2(lo, hi);
}

constexpr int D_DIM        = 1024;
constexpr int THREADS      = 256;
constexpr int ROWS_PER_BLK = 64;
constexpr int BATCH        = 16;
constexpr int PART_STRIDE  = 49;   // 48 used slots (16 rows * 3 pairs) + 1 pad, in ull

__global__ void __launch_bounds__(THREADS, 4)
q6_kernel(const float* __restrict__ x,
          const float* __restrict__ W,
          const float* __restrict__ proto,
          const float* __restrict__ hs,
          float* __restrict__ out)
{
    // partials: [g=0..63][row*3+pair], padded stride to kill bank conflicts
    __shared__ ull   part[64 * PART_STRIDE];
    __shared__ ull   zz[BATCH * 3];
    __shared__ float pn[8][6];
    __shared__ float s3_sh;

    const int tid  = threadIdx.x;
    const int lane = tid & 31;
    const int warp = tid >> 5;
    const int col  = tid * 4;        // this thread owns columns [col, col+4)

    // ---- one-time block init: normalized prototypes + fused scale ----
    if (tid < 8) {
        float v[6]; float ss = 0.f;
        #pragma unroll
        for (int k = 0; k < 6; ++k) { v[k] = proto[tid * 6 + k]; ss += v[k] * v[k]; }
        float n = fmaxf(sqrtf(ss), 1e-12f);
        #pragma unroll
        for (int k = 0; k < 6; ++k) pn[tid][k] = v[k] / n;
    }
    if (tid == 8) s3_sh = 3.0f * hs[0];   // softmax(-hs*(6-6d)/2) == softmax(3*hs*d)

    // ---- W slice for this thread's 4 columns, packed (k0,k1),(k2,k3),(k4,k5) ----
    ull wp[4][3];
    {
        float4 w4[6];
        #pragma unroll
        for (int k = 0; k < 6; ++k)
            w4[k] = *reinterpret_cast<const float4*>(W + k * D_DIM + col);
        #pragma unroll
        for (int p = 0; p < 3; ++p) {
            wp[0][p] = pack2(w4[2*p].x, w4[2*p+1].x);
            wp[1][p] = pack2(w4[2*p].y, w4[2*p+1].y);
            wp[2][p] = pack2(w4[2*p].z, w4[2*p+1].z);
            wp[3][p] = pack2(w4[2*p].w, w4[2*p+1].w);
        }
    }

    const int rowbase = blockIdx.x * ROWS_PER_BLK;

    for (int b = 0; b < ROWS_PER_BLK / BATCH; ++b) {
        const int    r0 = rowbase + b * BATCH;
        const float* xp = x + (size_t)r0 * D_DIM + col;

        // ---------------- phase 1: partial dots + 2-round butterfly ----------------
        #pragma unroll
        for (int r = 0; r < BATCH; r += 4) {
            float4 xv[4];
            #pragma unroll
            for (int u = 0; u < 4; ++u)   // batch 4 streaming loads -> MLP=4
                xv[u] = __ldcs(reinterpret_cast<const float4*>(xp + (size_t)(r + u) * D_DIM));
            #pragma unroll
            for (int u = 0; u < 4; ++u) {
                ull xx = dup2(xv[u].x);
                ull a0 = fmul2(xx, wp[0][0]);
                ull a1 = fmul2(xx, wp[0][1]);
                ull a2 = fmul2(xx, wp[0][2]);
                xx = dup2(xv[u].y);
                a0 = ffma2(xx, wp[1][0], a0);
                a1 = ffma2(xx, wp[1][1], a1);
                a2 = ffma2(xx, wp[1][2], a2);
                xx = dup2(xv[u].z);
                a0 = ffma2(xx, wp[2][0], a0);
                a1 = ffma2(xx, wp[2][1], a1);
                a2 = ffma2(xx, wp[2][2], a2);
                xx = dup2(xv[u].w);
                a0 = ffma2(xx, wp[3][0], a0);
                a1 = ffma2(xx, wp[3][1], a1);
                a2 = ffma2(xx, wp[3][2], a2);

                // reduce lanes {l, l^1} then {l, l^2}: lane%4==0 holds group-of-4 sum
                a0 = fadd2(a0, __shfl_xor_sync(0xffffffffu, a0, 1));
                a1 = fadd2(a1, __shfl_xor_sync(0xffffffffu, a1, 1));
                a2 = fadd2(a2, __shfl_xor_sync(0xffffffffu, a2, 1));
                a0 = fadd2(a0, __shfl_xor_sync(0xffffffffu, a0, 2));
                a1 = fadd2(a1, __shfl_xor_sync(0xffffffffu, a1, 2));
                a2 = fadd2(a2, __shfl_xor_sync(0xffffffffu, a2, 2));

                if ((lane & 3) == 0) {
                    const int g = warp * 8 + (lane >> 2);   // 0..63
                    ull* dst = part + g * PART_STRIDE + (r + u) * 3;
                    dst[0] = a0; dst[1] = a1; dst[2] = a2;
                }
            }
        }
        __syncthreads();

        // ------- phase 2: 48 threads sum 64 group partials per (row, pair), MLP=8 -----
        if (tid < BATCH * 3) {
            ull s[8];
            #pragma unroll
            for (int j = 0; j < 8; ++j)               // 8 independent loads in flight
                s[j] = part[j * PART_STRIDE + tid];
            #pragma unroll
            for (int g = 8; g < 64; g += 8) {
                #pragma unroll
                for (int j = 0; j < 8; ++j)
                    s[j] = fadd2(s[j], part[(g + j) * PART_STRIDE + tid]);
            }
            ull t0 = fadd2(fadd2(s[0], s[1]), fadd2(s[2], s[3]));
            ull t1 = fadd2(fadd2(s[4], s[5]), fadd2(s[6], s[7]));
            zz[tid] = fadd2(t0, t1);
        }
        __syncthreads();

        // ---------------- phase 3: epilogue, one thread per row --------------------
        // (overlaps other warps' next-batch streaming; MUFU-based fast math)
        if (tid < BATCH) {
            float z[6];
            #pragma unroll
            for (int p = 0; p < 3; ++p) {
                float2 v = unpack2(zz[tid * 3 + p]);
                z[2*p] = v.x; z[2*p + 1] = v.y;
            }
            float ss = 0.f;
            #pragma unroll
            for (int k = 0; k < 6; ++k) {
                float e2 = __expf(2.0f * z[k]);            // tanh = 1 - 2/(e^2x+1)
                z[k] = 1.0f - __fdividef(2.0f, e2 + 1.0f);
                ss += z[k] * z[k];
            }
            const float sc = __fdividef(s3_sh, fmaxf(sqrtf(ss), 1e-6f));

            float e[8]; float sum = 0.f;
            #pragma unroll
            for (int p = 0; p < 8; ++p) {
                float d = 0.f;
                #pragma unroll
                for (int k = 0; k < 6; ++k) d += z[k] * pn[p][k];
                e[p] = __expf(sc * d);
                sum += e[p];
            }
            const float rs  = __fdividef(1.0f, sum);
            const int   row = r0 + tid;
            float4* op = reinterpret_cast<float4*>(out + (size_t)row * 8);
            op[0] = make_float4(e[0]*rs, e[1]*rs, e[2]*rs, e[3]*rs);
            op[1] = make_float4(e[4]*rs, e[5]*rs, e[6]*rs, e[7]*rs);
        }
    }
}

extern "C" void kernel_launch(void* const* d_in, const int* in_sizes, int n_in,
                              void* d_out, int out_size) {
    const float* x     = (const float*)d_in[0];
    const float* W     = (const float*)d_in[1];
    const float* proto = (const float*)d_in[2];
    const float* hs    = (const float*)d_in[3];
    float* out = (float*)d_out;

    const int n_rows = in_sizes[0] / D_DIM;          // 32768
    const int grid   = n_rows / ROWS_PER_BLK;        // 512
    q6_kernel<<<grid, THREADS>>>(x, W, proto, hs, out);
}